// round 1
// baseline (speedup 1.0000x reference)
#include <cuda_runtime.h>
#include <math.h>

#define N_NODES 50000
#define N_EDGES 800000
#define DIM     128
#define K2      256   // concat of h and S*h

// ---------------- scratch (static device globals; no allocation) ----------------
__device__ float g_h[2][(size_t)N_NODES * DIM];   // ping-pong hidden states
__device__ float g_agg[(size_t)N_NODES * DIM];    // S*h (neighbor sum, no self loop)
__device__ float g_colsum[DIM];                   // sum_i h[i][:]
__device__ float g_rvec[DIM];                     // Vb+Ab+Rb + Rw @ colsum

// ---------------- zero agg + colsum ----------------
__global__ void zero_kernel() {
    int idx    = blockIdx.x * blockDim.x + threadIdx.x;
    int stride = gridDim.x * blockDim.x;
    float4* p  = (float4*)g_agg;
    const int n4 = (N_NODES * DIM) / 4;
    for (int i = idx; i < n4; i += stride) p[i] = make_float4(0.f, 0.f, 0.f, 0.f);
    if (blockIdx.x == 0 && threadIdx.x < DIM) g_colsum[threadIdx.x] = 0.f;
}

// ---------------- column sum of h (readout) ----------------
__global__ void colsum_kernel(const float* __restrict__ h) {
    int col = threadIdx.x;  // blockDim.x == 128
    float s = 0.f;
    for (int r = blockIdx.x; r < N_NODES; r += gridDim.x)
        s += h[(size_t)r * DIM + col];
    atomicAdd(&g_colsum[col], s);
}

// ---------------- edge scatter: agg[dst] += h[src], one warp per edge ----------------
__global__ void scatter_kernel(const float* __restrict__ h,
                               const int* __restrict__ src,
                               const int* __restrict__ dst) {
    int gtid = blockIdx.x * blockDim.x + threadIdx.x;
    int e    = gtid >> 5;
    int lane = threadIdx.x & 31;
    if (e >= N_EDGES) return;
    int s = __ldg(&src[e]);
    int d = __ldg(&dst[e]);
    const float4* hp = (const float4*)(h + (size_t)s * DIM);
    float4 v = hp[lane];
    float* ap = g_agg + (size_t)d * DIM + lane * 4;
    asm volatile("red.global.add.v4.f32 [%0], {%1,%2,%3,%4};"
                 :: "l"(ap), "f"(v.x), "f"(v.y), "f"(v.z), "f"(v.w) : "memory");
}

// ---------------- effective bias: rvec = Vb + Ab + Rb + Rw @ colsum ----------------
__global__ void rvec_kernel(const float* __restrict__ Vb, const float* __restrict__ Ab,
                            const float* __restrict__ Rb, const float* __restrict__ Rw,
                            int layer) {
    int j = threadIdx.x;  // 128 threads
    const float* rw = Rw + (size_t)layer * DIM * DIM + (size_t)j * DIM;
    float s = Vb[layer * DIM + j] + Ab[layer * DIM + j] + Rb[layer * DIM + j];
    #pragma unroll 8
    for (int k = 0; k < DIM; k++) s += rw[k] * g_colsum[k];
    g_rvec[j] = s;
}

// ---------------- fused combine GEMM ----------------
// hout[i][j] = relu( sum_k h[i][k]*(Vw+Aw)[j][k] + sum_k agg[i][k]*Aw[j][k] + rvec[j] )
// Tiled SGEMM: BM=128 rows x 128 cols per block, K=256 (first 128 from h, last 128 from agg),
// BK=16, 256 threads, 8x8 register micro-tile.
#define BM 128
#define BK 16

__global__ __launch_bounds__(256) void gemm_kernel(const float* __restrict__ h,
                                                   const float* __restrict__ Vw,  // layer-offset
                                                   const float* __restrict__ Aw,  // layer-offset
                                                   float* __restrict__ hout) {
    __shared__ float As[BK][BM];   // A tile, k-major
    __shared__ float Ws[BK][BM];   // W tile, k-major (W[j][k] transposed)

    const int tid  = threadIdx.x;
    const int row0 = blockIdx.x * BM;
    const int tr   = tid >> 4;   // 0..15  (row group)
    const int tc   = tid & 15;   // 0..15  (col group)

    float acc[8][8];
    #pragma unroll
    for (int i = 0; i < 8; i++)
        #pragma unroll
        for (int j = 0; j < 8; j++) acc[i][j] = 0.f;

    #pragma unroll 1
    for (int kc = 0; kc < K2 / BK; kc++) {
        const int k0 = kc * BK;
        const bool first_half = (k0 < DIM);
        const float* Asrc = first_half ? h : g_agg;
        const int kb = k0 & (DIM - 1);

        // load A tile: 128 rows x 16 k = 512 float4, 2 per thread
        #pragma unroll
        for (int it = 0; it < 2; it++) {
            int idx = tid + it * 256;
            int r   = idx >> 2;
            int kq  = idx & 3;
            int gr  = row0 + r;
            float4 v = make_float4(0.f, 0.f, 0.f, 0.f);
            if (gr < N_NODES)
                v = *(const float4*)(Asrc + (size_t)gr * DIM + kb + kq * 4);
            As[kq * 4 + 0][r] = v.x;
            As[kq * 4 + 1][r] = v.y;
            As[kq * 4 + 2][r] = v.z;
            As[kq * 4 + 3][r] = v.w;
        }
        // load W tile transposed: Ws[kk][j] = (k<128 ? Vw[j][k]+Aw[j][k] : Aw[j][k-128])
        #pragma unroll
        for (int it = 0; it < 2; it++) {
            int idx = tid + it * 256;
            int j   = idx >> 2;
            int kq  = idx & 3;
            float4 w = *(const float4*)(Aw + (size_t)j * DIM + kb + kq * 4);
            if (first_half) {
                float4 v2 = *(const float4*)(Vw + (size_t)j * DIM + kb + kq * 4);
                w.x += v2.x; w.y += v2.y; w.z += v2.z; w.w += v2.w;
            }
            Ws[kq * 4 + 0][j] = w.x;
            Ws[kq * 4 + 1][j] = w.y;
            Ws[kq * 4 + 2][j] = w.z;
            Ws[kq * 4 + 3][j] = w.w;
        }
        __syncthreads();

        #pragma unroll
        for (int kk = 0; kk < BK; kk++) {
            float a[8], w[8];
            *(float4*)(a + 0) = *(const float4*)&As[kk][tr * 8 + 0];
            *(float4*)(a + 4) = *(const float4*)&As[kk][tr * 8 + 4];
            *(float4*)(w + 0) = *(const float4*)&Ws[kk][tc * 8 + 0];
            *(float4*)(w + 4) = *(const float4*)&Ws[kk][tc * 8 + 4];
            #pragma unroll
            for (int i = 0; i < 8; i++)
                #pragma unroll
                for (int j = 0; j < 8; j++) acc[i][j] += a[i] * w[j];
        }
        __syncthreads();
    }

    // epilogue: + rvec, relu, store
    float rv[8];
    *(float4*)(rv + 0) = *(const float4*)&g_rvec[tc * 8 + 0];
    *(float4*)(rv + 4) = *(const float4*)&g_rvec[tc * 8 + 4];

    #pragma unroll
    for (int i = 0; i < 8; i++) {
        int gr = row0 + tr * 8 + i;
        if (gr < N_NODES) {
            float o[8];
            #pragma unroll
            for (int j = 0; j < 8; j++) o[j] = fmaxf(acc[i][j] + rv[j], 0.f);
            *(float4*)(hout + (size_t)gr * DIM + tc * 8 + 0) = make_float4(o[0], o[1], o[2], o[3]);
            *(float4*)(hout + (size_t)gr * DIM + tc * 8 + 4) = make_float4(o[4], o[5], o[6], o[7]);
        }
    }
}

// ---------------- output head: sigmoid(h @ out_w^T + out_b), one warp per node ----------------
__global__ void out_kernel(const float* __restrict__ h,
                           const float* __restrict__ ow,
                           const float* __restrict__ ob,
                           float* __restrict__ out) {
    int gtid = blockIdx.x * blockDim.x + threadIdx.x;
    int node = gtid >> 5;
    int lane = threadIdx.x & 31;
    if (node >= N_NODES) return;
    const float4* hp = (const float4*)(h + (size_t)node * DIM);
    float4 v  = hp[lane];
    float4 w0 = ((const float4*)ow)[lane];
    float4 w1 = ((const float4*)(ow + DIM))[lane];
    float s0 = v.x * w0.x + v.y * w0.y + v.z * w0.z + v.w * w0.w;
    float s1 = v.x * w1.x + v.y * w1.y + v.z * w1.z + v.w * w1.w;
    #pragma unroll
    for (int off = 16; off > 0; off >>= 1) {
        s0 += __shfl_down_sync(0xffffffffu, s0, off);
        s1 += __shfl_down_sync(0xffffffffu, s1, off);
    }
    if (lane == 0) {
        out[(size_t)node * 2 + 0] = 1.f / (1.f + expf(-(s0 + ob[0])));
        out[(size_t)node * 2 + 1] = 1.f / (1.f + expf(-(s1 + ob[1])));
    }
}

// ---------------- launch ----------------
extern "C" void kernel_launch(void* const* d_in, const int* in_sizes, int n_in,
                              void* d_out, int out_size) {
    const float* x   = (const float*)d_in[0];
    const int*   src = (const int*)  d_in[1];
    const int*   dst = (const int*)  d_in[2];
    const float* Vw  = (const float*)d_in[3];
    const float* Vb  = (const float*)d_in[4];
    const float* Aw  = (const float*)d_in[5];
    const float* Ab  = (const float*)d_in[6];
    const float* Rw  = (const float*)d_in[7];
    const float* Rb  = (const float*)d_in[8];
    const float* ow  = (const float*)d_in[9];
    const float* ob  = (const float*)d_in[10];
    float* out = (float*)d_out;

    float* hbuf = nullptr;
    cudaGetSymbolAddress((void**)&hbuf, g_h);
    float* h0 = hbuf;
    float* h1 = hbuf + (size_t)N_NODES * DIM;

    const int gemm_blocks    = (N_NODES + BM - 1) / BM;           // 391
    const int scatter_blocks = (N_EDGES * 32 + 255) / 256;        // 100000
    const int out_blocks     = (N_NODES * 32 + 255) / 256;

    const float* hin = x;
    float* bufs[2] = {h0, h1};
    for (int l = 0; l < 3; l++) {
        float* hout = bufs[l & 1];
        zero_kernel<<<1024, 256>>>();
        colsum_kernel<<<512, 128>>>(hin);
        scatter_kernel<<<scatter_blocks, 256>>>(hin, src, dst);
        rvec_kernel<<<1, 128>>>(Vb, Ab, Rb, Rw, l);
        gemm_kernel<<<gemm_blocks, 256>>>(hin,
                                          Vw + (size_t)l * DIM * DIM,
                                          Aw + (size_t)l * DIM * DIM,
                                          hout);
        hin = hout;
    }
    out_kernel<<<out_blocks, 256>>>(hin, ow, ob, out);
}

// round 2
// speedup vs baseline: 1.3348x; 1.3348x over previous
#include <cuda_runtime.h>
#include <math.h>

#define N_NODES 50000
#define N_EDGES 800000
#define DIM     128
#define K2      256
#define BM      128
#define BK      16

typedef unsigned long long u64;

// ---------------- scratch ----------------
__device__ float g_h[2][(size_t)N_NODES * DIM];
__device__ float g_agg[(size_t)N_NODES * DIM];
__device__ float g_cs[2][DIM];          // ping-pong column sums (readout)
__device__ float g_rvec[DIM];
__device__ int   g_deg[N_NODES];
__device__ int   g_cur[N_NODES];
__device__ int   g_rowptr[N_NODES + 1];
__device__ int   g_csrc[N_EDGES];

// ---------------- f32x2 helpers ----------------
__device__ __forceinline__ void fma2(u64& acc, u64 a, u64 b) {
    asm("fma.rn.f32x2 %0, %1, %2, %0;" : "+l"(acc) : "l"(a), "l"(b));
}
__device__ __forceinline__ u64 dup2(float a) {
    u64 r; asm("mov.b64 %0, {%1, %1};" : "=l"(r) : "f"(a)); return r;
}

// ---------------- init: zero deg/cursor/colsum[0] ----------------
__global__ void init_kernel() {
    int idx = blockIdx.x * blockDim.x + threadIdx.x;
    int stride = gridDim.x * blockDim.x;
    for (int i = idx; i < N_NODES; i += stride) { g_deg[i] = 0; g_cur[i] = 0; }
    if (blockIdx.x == 0 && threadIdx.x < DIM) g_cs[0][threadIdx.x] = 0.f;
}

// ---------------- CSR build ----------------
__global__ void deg_hist_kernel(const int* __restrict__ dst) {
    int idx = blockIdx.x * blockDim.x + threadIdx.x;
    int stride = gridDim.x * blockDim.x;
    for (int e = idx; e < N_EDGES; e += stride) atomicAdd(&g_deg[dst[e]], 1);
}

__global__ void scan_kernel() {   // 1 block, 1024 threads
    __shared__ int sm[1024];
    const int CHUNK = (N_NODES + 1023) / 1024;  // 49
    int t = threadIdx.x;
    int base = t * CHUNK;
    int s = 0;
    for (int i = 0; i < CHUNK; i++) {
        int idx = base + i;
        if (idx < N_NODES) s += g_deg[idx];
    }
    sm[t] = s;
    __syncthreads();
    for (int off = 1; off < 1024; off <<= 1) {
        int v = (t >= off) ? sm[t - off] : 0;
        __syncthreads();
        sm[t] += v;
        __syncthreads();
    }
    int run = (t == 0) ? 0 : sm[t - 1];
    for (int i = 0; i < CHUNK; i++) {
        int idx = base + i;
        if (idx < N_NODES) { g_rowptr[idx] = run; run += g_deg[idx]; }
    }
    if (t == 1023) g_rowptr[N_NODES] = run;
}

__global__ void fill_kernel(const int* __restrict__ src, const int* __restrict__ dst) {
    int idx = blockIdx.x * blockDim.x + threadIdx.x;
    int stride = gridDim.x * blockDim.x;
    for (int e = idx; e < N_EDGES; e += stride) {
        int d = dst[e];
        int p = atomicAdd(&g_cur[d], 1);
        g_csrc[g_rowptr[d] + p] = src[e];
    }
}

// ---------------- colsum of input x into g_cs[0] ----------------
__global__ void colsum_x_kernel(const float* __restrict__ h) {
    int col = threadIdx.x;  // 128 threads
    float s = 0.f;
    for (int r = blockIdx.x; r < N_NODES; r += gridDim.x)
        s += h[(size_t)r * DIM + col];
    atomicAdd(&g_cs[0][col], s);
}

// ---------------- rvec: g_rvec = Vb+Ab+Rb + Rw @ cs[buf]; also zero cs[buf^1] ----------------
__global__ void rvec_kernel(const float* __restrict__ Vb, const float* __restrict__ Ab,
                            const float* __restrict__ Rb, const float* __restrict__ Rw,
                            int layer, int buf) {
    int gt = blockIdx.x * blockDim.x + threadIdx.x;
    if (blockIdx.x == 0 && threadIdx.x < DIM) g_cs[buf ^ 1][threadIdx.x] = 0.f;
    int gw = gt >> 5;            // warp id == output j
    int lane = threadIdx.x & 31;
    if (gw >= DIM) return;
    const float4* rw = (const float4*)(Rw + (size_t)layer * DIM * DIM + (size_t)gw * DIM);
    const float4* cs = (const float4*)g_cs[buf];
    float4 r = rw[lane];
    float4 c = cs[lane];
    float s = r.x * c.x + r.y * c.y + r.z * c.z + r.w * c.w;
    #pragma unroll
    for (int off = 16; off > 0; off >>= 1) s += __shfl_down_sync(0xffffffffu, s, off);
    if (lane == 0)
        g_rvec[gw] = s + Vb[layer * DIM + gw] + Ab[layer * DIM + gw] + Rb[layer * DIM + gw];
}

// ---------------- gather: agg[n] = sum over in-neighbors of h[src] ----------------
__global__ void gather_kernel(const float* __restrict__ h) {
    int gt = blockIdx.x * blockDim.x + threadIdx.x;
    int node = gt >> 5;
    int lane = threadIdx.x & 31;
    if (node >= N_NODES) return;
    int beg = g_rowptr[node];
    int end = g_rowptr[node + 1];
    float4 acc = make_float4(0.f, 0.f, 0.f, 0.f);
    int j = beg;
    for (; j + 4 <= end; j += 4) {
        int s0 = g_csrc[j], s1 = g_csrc[j + 1], s2 = g_csrc[j + 2], s3 = g_csrc[j + 3];
        float4 v0 = *(const float4*)(h + (size_t)s0 * DIM + lane * 4);
        float4 v1 = *(const float4*)(h + (size_t)s1 * DIM + lane * 4);
        float4 v2 = *(const float4*)(h + (size_t)s2 * DIM + lane * 4);
        float4 v3 = *(const float4*)(h + (size_t)s3 * DIM + lane * 4);
        acc.x += v0.x + v1.x + v2.x + v3.x;
        acc.y += v0.y + v1.y + v2.y + v3.y;
        acc.z += v0.z + v1.z + v2.z + v3.z;
        acc.w += v0.w + v1.w + v2.w + v3.w;
    }
    for (; j < end; j++) {
        int s = g_csrc[j];
        float4 v = *(const float4*)(h + (size_t)s * DIM + lane * 4);
        acc.x += v.x; acc.y += v.y; acc.z += v.z; acc.w += v.w;
    }
    *(float4*)(g_agg + (size_t)node * DIM + lane * 4) = acc;
}

// ---------------- fused combine GEMM (f32x2) + colsum epilogue ----------------
// hout[i][j] = relu( h[i]·(Vw+Aw)[j] + agg[i]·Aw[j] + rvec[j] )
// accumulates column sums of hout into g_cs[csbuf]
union F4U {
    float4 f4;
    u64    u[2];
    float  f[4];
};

__global__ __launch_bounds__(256) void gemm_kernel(const float* __restrict__ h,
                                                   const float* __restrict__ Vw,
                                                   const float* __restrict__ Aw,
                                                   float* __restrict__ hout,
                                                   int csbuf) {
    __shared__ float As[BK][BM];
    __shared__ float Ws[BK][BM];
    __shared__ float cs_s[DIM];

    const int tid  = threadIdx.x;
    const int row0 = blockIdx.x * BM;
    const int tr   = tid >> 4;
    const int tc   = tid & 15;

    if (tid < DIM) cs_s[tid] = 0.f;

    u64 acc[8][4];
    #pragma unroll
    for (int i = 0; i < 8; i++)
        #pragma unroll
        for (int j = 0; j < 4; j++) acc[i][j] = 0ull;

    #pragma unroll 1
    for (int kc = 0; kc < K2 / BK; kc++) {
        const int k0 = kc * BK;
        const bool first_half = (k0 < DIM);
        const float* Asrc = first_half ? h : g_agg;
        const int kb = k0 & (DIM - 1);

        #pragma unroll
        for (int it = 0; it < 2; it++) {
            int idx = tid + it * 256;
            int r   = idx >> 2;
            int kq  = idx & 3;
            int gr  = row0 + r;
            float4 v = make_float4(0.f, 0.f, 0.f, 0.f);
            if (gr < N_NODES)
                v = *(const float4*)(Asrc + (size_t)gr * DIM + kb + kq * 4);
            As[kq * 4 + 0][r] = v.x;
            As[kq * 4 + 1][r] = v.y;
            As[kq * 4 + 2][r] = v.z;
            As[kq * 4 + 3][r] = v.w;
        }
        #pragma unroll
        for (int it = 0; it < 2; it++) {
            int idx = tid + it * 256;
            int j   = idx >> 2;
            int kq  = idx & 3;
            float4 w = *(const float4*)(Aw + (size_t)j * DIM + kb + kq * 4);
            if (first_half) {
                float4 v2 = *(const float4*)(Vw + (size_t)j * DIM + kb + kq * 4);
                w.x += v2.x; w.y += v2.y; w.z += v2.z; w.w += v2.w;
            }
            Ws[kq * 4 + 0][j] = w.x;
            Ws[kq * 4 + 1][j] = w.y;
            Ws[kq * 4 + 2][j] = w.z;
            Ws[kq * 4 + 3][j] = w.w;
        }
        __syncthreads();

        #pragma unroll
        for (int kk = 0; kk < BK; kk++) {
            float a[8];
            *(float4*)(a + 0) = *(const float4*)&As[kk][tr * 8 + 0];
            *(float4*)(a + 4) = *(const float4*)&As[kk][tr * 8 + 4];
            F4U w0, w1;
            w0.f4 = *(const float4*)&Ws[kk][tc * 8 + 0];
            w1.f4 = *(const float4*)&Ws[kk][tc * 8 + 4];
            u64 ad[8];
            #pragma unroll
            for (int i = 0; i < 8; i++) ad[i] = dup2(a[i]);
            #pragma unroll
            for (int i = 0; i < 8; i++) {
                fma2(acc[i][0], ad[i], w0.u[0]);
                fma2(acc[i][1], ad[i], w0.u[1]);
                fma2(acc[i][2], ad[i], w1.u[0]);
                fma2(acc[i][3], ad[i], w1.u[1]);
            }
        }
        __syncthreads();
    }

    // epilogue: + rvec, relu, store, colsum
    float rv[8];
    *(float4*)(rv + 0) = *(const float4*)&g_rvec[tc * 8 + 0];
    *(float4*)(rv + 4) = *(const float4*)&g_rvec[tc * 8 + 4];

    float colpart[8];
    #pragma unroll
    for (int j = 0; j < 8; j++) colpart[j] = 0.f;

    #pragma unroll
    for (int i = 0; i < 8; i++) {
        int gr = row0 + tr * 8 + i;
        if (gr < N_NODES) {
            F4U lo, hi;
            lo.u[0] = acc[i][0]; lo.u[1] = acc[i][1];
            hi.u[0] = acc[i][2]; hi.u[1] = acc[i][3];
            float o[8];
            #pragma unroll
            for (int j = 0; j < 4; j++) o[j]     = fmaxf(lo.f[j] + rv[j],     0.f);
            #pragma unroll
            for (int j = 0; j < 4; j++) o[j + 4] = fmaxf(hi.f[j] + rv[j + 4], 0.f);
            #pragma unroll
            for (int j = 0; j < 8; j++) colpart[j] += o[j];
            *(float4*)(hout + (size_t)gr * DIM + tc * 8 + 0) = make_float4(o[0], o[1], o[2], o[3]);
            *(float4*)(hout + (size_t)gr * DIM + tc * 8 + 4) = make_float4(o[4], o[5], o[6], o[7]);
        }
    }
    #pragma unroll
    for (int j = 0; j < 8; j++) atomicAdd(&cs_s[tc * 8 + j], colpart[j]);
    __syncthreads();
    if (tid < DIM) atomicAdd(&g_cs[csbuf][tid], cs_s[tid]);
}

// ---------------- output head ----------------
__global__ void out_kernel(const float* __restrict__ h,
                           const float* __restrict__ ow,
                           const float* __restrict__ ob,
                           float* __restrict__ out) {
    int gtid = blockIdx.x * blockDim.x + threadIdx.x;
    int node = gtid >> 5;
    int lane = threadIdx.x & 31;
    if (node >= N_NODES) return;
    const float4* hp = (const float4*)(h + (size_t)node * DIM);
    float4 v  = hp[lane];
    float4 w0 = ((const float4*)ow)[lane];
    float4 w1 = ((const float4*)(ow + DIM))[lane];
    float s0 = v.x * w0.x + v.y * w0.y + v.z * w0.z + v.w * w0.w;
    float s1 = v.x * w1.x + v.y * w1.y + v.z * w1.z + v.w * w1.w;
    #pragma unroll
    for (int off = 16; off > 0; off >>= 1) {
        s0 += __shfl_down_sync(0xffffffffu, s0, off);
        s1 += __shfl_down_sync(0xffffffffu, s1, off);
    }
    if (lane == 0) {
        out[(size_t)node * 2 + 0] = 1.f / (1.f + expf(-(s0 + ob[0])));
        out[(size_t)node * 2 + 1] = 1.f / (1.f + expf(-(s1 + ob[1])));
    }
}

// ---------------- launch ----------------
extern "C" void kernel_launch(void* const* d_in, const int* in_sizes, int n_in,
                              void* d_out, int out_size) {
    const float* x   = (const float*)d_in[0];
    const int*   src = (const int*)  d_in[1];
    const int*   dst = (const int*)  d_in[2];
    const float* Vw  = (const float*)d_in[3];
    const float* Vb  = (const float*)d_in[4];
    const float* Aw  = (const float*)d_in[5];
    const float* Ab  = (const float*)d_in[6];
    const float* Rw  = (const float*)d_in[7];
    const float* Rb  = (const float*)d_in[8];
    const float* ow  = (const float*)d_in[9];
    const float* ob  = (const float*)d_in[10];
    float* out = (float*)d_out;

    float* hbuf = nullptr;
    cudaGetSymbolAddress((void**)&hbuf, g_h);
    float* h0 = hbuf;
    float* h1 = hbuf + (size_t)N_NODES * DIM;

    const int gemm_blocks   = (N_NODES + BM - 1) / BM;        // 391
    const int edge_blocks   = (N_EDGES + 255) / 256;          // 3125
    const int warp_blocks   = (N_NODES * 32 + 255) / 256;     // 6250

    // CSR build (once per launch)
    init_kernel<<<64, 256>>>();
    deg_hist_kernel<<<edge_blocks, 256>>>(dst);
    scan_kernel<<<1, 1024>>>();
    fill_kernel<<<edge_blocks, 256>>>(src, dst);
    colsum_x_kernel<<<512, 128>>>(x);

    const float* hin = x;
    float* bufs[2] = {h0, h1};
    for (int l = 0; l < 3; l++) {
        float* hout = bufs[l & 1];
        int buf = l & 1;
        rvec_kernel<<<16, 256>>>(Vb, Ab, Rb, Rw, l, buf);
        gather_kernel<<<warp_blocks, 256>>>(hin);
        gemm_kernel<<<gemm_blocks, 256>>>(hin,
                                          Vw + (size_t)l * DIM * DIM,
                                          Aw + (size_t)l * DIM * DIM,
                                          hout, buf ^ 1);
        hin = hout;
    }
    out_kernel<<<warp_blocks, 256>>>(hin, ow, ob, out);
}

// round 4
// speedup vs baseline: 2.9475x; 2.2082x over previous
#include <cuda_runtime.h>
#include <cuda_bf16.h>
#include <math.h>
#include <cstdint>

#define N_NODES 50000
#define N_EDGES 800000
#define DIM     128
#define K2      256
#define BM      128
#define STRIDE  264   // padded smem row stride in bf16 elems (528 B)

// ======================= scratch =======================
__device__ __nv_bfloat16 g_hb[2][(size_t)N_NODES * K2];   // cols 0-127 = h, 128-255 = agg
__device__ __nv_bfloat16 g_w2[3][(size_t)DIM * K2];       // [j][k] combined weights
__device__ __align__(16) float g_cs[2][DIM];
__device__ __align__(16) float g_rvec[DIM];
__device__ int g_deg[N_NODES];
__device__ int g_cur[N_NODES];
__device__ int g_rowptr[N_NODES + 1];
__device__ int g_csrc[N_EDGES];

// ======================= PTX helpers (sm_80-level only) =======================
__device__ __forceinline__ uint32_t smem_to_u32(const void* p) {
    uint32_t a;
    asm("{ .reg .u64 t; cvta.to.shared.u64 t, %1; cvt.u32.u64 %0, t; }" : "=r"(a) : "l"(p));
    return a;
}
__device__ __forceinline__ void ldsm_x4(uint32_t* r, uint32_t addr) {
    asm volatile("ldmatrix.sync.aligned.m8n8.x4.shared.b16 {%0,%1,%2,%3}, [%4];"
                 : "=r"(r[0]), "=r"(r[1]), "=r"(r[2]), "=r"(r[3]) : "r"(addr));
}
__device__ __forceinline__ void ldsm_x2(uint32_t* r, uint32_t addr) {
    asm volatile("ldmatrix.sync.aligned.m8n8.x2.shared.b16 {%0,%1}, [%2];"
                 : "=r"(r[0]), "=r"(r[1]) : "r"(addr));
}
__device__ __forceinline__ void mma16816(float* c, const uint32_t* a, const uint32_t* b) {
    asm volatile("mma.sync.aligned.m16n8k16.row.col.f32.bf16.bf16.f32 "
                 "{%0,%1,%2,%3}, {%4,%5,%6,%7}, {%8,%9}, {%0,%1,%2,%3};"
                 : "+f"(c[0]), "+f"(c[1]), "+f"(c[2]), "+f"(c[3])
                 : "r"(a[0]), "r"(a[1]), "r"(a[2]), "r"(a[3]), "r"(b[0]), "r"(b[1]));
}

// ======================= CSR build =======================
__global__ void init_kernel() {
    int idx = blockIdx.x * blockDim.x + threadIdx.x;
    int stride = gridDim.x * blockDim.x;
    for (int i = idx; i < N_NODES; i += stride) { g_deg[i] = 0; g_cur[i] = 0; }
    if (blockIdx.x == 0 && threadIdx.x < DIM) g_cs[0][threadIdx.x] = 0.f;
}
__global__ void deg_hist_kernel(const int* __restrict__ dst) {
    int idx = blockIdx.x * blockDim.x + threadIdx.x;
    int stride = gridDim.x * blockDim.x;
    for (int e = idx; e < N_EDGES; e += stride) atomicAdd(&g_deg[dst[e]], 1);
}
__global__ void scan_kernel() {   // 1 block, 1024 threads
    __shared__ int sm[1024];
    const int CHUNK = (N_NODES + 1023) / 1024;
    int t = threadIdx.x;
    int base = t * CHUNK;
    int s = 0;
    for (int i = 0; i < CHUNK; i++) { int idx = base + i; if (idx < N_NODES) s += g_deg[idx]; }
    sm[t] = s;
    __syncthreads();
    for (int off = 1; off < 1024; off <<= 1) {
        int v = (t >= off) ? sm[t - off] : 0;
        __syncthreads();
        sm[t] += v;
        __syncthreads();
    }
    int run = (t == 0) ? 0 : sm[t - 1];
    for (int i = 0; i < CHUNK; i++) {
        int idx = base + i;
        if (idx < N_NODES) { g_rowptr[idx] = run; run += g_deg[idx]; }
    }
    if (t == 1023) g_rowptr[N_NODES] = run;
}
__global__ void fill_kernel(const int* __restrict__ src, const int* __restrict__ dst) {
    int idx = blockIdx.x * blockDim.x + threadIdx.x;
    int stride = gridDim.x * blockDim.x;
    for (int e = idx; e < N_EDGES; e += stride) {
        int d = dst[e];
        int p = atomicAdd(&g_cur[d], 1);
        g_csrc[g_rowptr[d] + p] = src[e];
    }
}

// ======================= x -> bf16 + colsum =======================
__global__ void xconv_kernel(const float* __restrict__ x) {
    int col = threadIdx.x;  // 128 threads
    float s = 0.f;
    for (int r = blockIdx.x; r < N_NODES; r += gridDim.x) {
        float v = x[(size_t)r * DIM + col];
        g_hb[0][(size_t)r * K2 + col] = __float2bfloat16(v);
        s += v;
    }
    atomicAdd(&g_cs[0][col], s);
}

// ======================= W2 prep =======================
__global__ void w2prep_kernel(const float* __restrict__ Vw, const float* __restrict__ Aw) {
    int idx = blockIdx.x * blockDim.x + threadIdx.x;
    if (idx >= 3 * DIM * K2) return;
    int l = idx / (DIM * K2);
    int rem = idx % (DIM * K2);
    int j = rem >> 8;
    int k = rem & 255;
    float v;
    if (k < DIM) v = Vw[(size_t)l * DIM * DIM + j * DIM + k] + Aw[(size_t)l * DIM * DIM + j * DIM + k];
    else         v = Aw[(size_t)l * DIM * DIM + j * DIM + (k - DIM)];
    g_w2[l][(size_t)j * K2 + k] = __float2bfloat16(v);
}

// ======================= rvec =======================
__global__ void rvec_kernel(const float* __restrict__ Vb, const float* __restrict__ Ab,
                            const float* __restrict__ Rb, const float* __restrict__ Rw,
                            int layer, int buf) {
    int gt = blockIdx.x * blockDim.x + threadIdx.x;
    if (blockIdx.x == 0 && threadIdx.x < DIM) g_cs[buf ^ 1][threadIdx.x] = 0.f;
    int gw = gt >> 5;
    int lane = threadIdx.x & 31;
    if (gw >= DIM) return;
    const float4* rw = (const float4*)(Rw + (size_t)layer * DIM * DIM + (size_t)gw * DIM);
    const float4* cs = (const float4*)g_cs[buf];
    float4 r = rw[lane];
    float4 c = cs[lane];
    float s = r.x * c.x + r.y * c.y + r.z * c.z + r.w * c.w;
    #pragma unroll
    for (int off = 16; off > 0; off >>= 1) s += __shfl_down_sync(0xffffffffu, s, off);
    if (lane == 0)
        g_rvec[gw] = s + Vb[layer * DIM + gw] + Ab[layer * DIM + gw] + Rb[layer * DIM + gw];
}

// ======================= gather (bf16 in/out, fp32 accum) =======================
__global__ void gather_kernel(__nv_bfloat16* __restrict__ hb) {
    int gt = blockIdx.x * blockDim.x + threadIdx.x;
    int node = gt >> 5;
    int lane = threadIdx.x & 31;
    if (node >= N_NODES) return;
    int beg = g_rowptr[node];
    int end = g_rowptr[node + 1];
    float4 acc = make_float4(0.f, 0.f, 0.f, 0.f);
    int j = beg;
    #pragma unroll 1
    for (; j + 4 <= end; j += 4) {
        int s0 = g_csrc[j], s1 = g_csrc[j + 1], s2 = g_csrc[j + 2], s3 = g_csrc[j + 3];
        uint2 u0 = *(const uint2*)(hb + (size_t)s0 * K2 + lane * 4);
        uint2 u1 = *(const uint2*)(hb + (size_t)s1 * K2 + lane * 4);
        uint2 u2 = *(const uint2*)(hb + (size_t)s2 * K2 + lane * 4);
        uint2 u3 = *(const uint2*)(hb + (size_t)s3 * K2 + lane * 4);
        float2 a0 = __bfloat1622float2(*(__nv_bfloat162*)&u0.x);
        float2 b0 = __bfloat1622float2(*(__nv_bfloat162*)&u0.y);
        float2 a1 = __bfloat1622float2(*(__nv_bfloat162*)&u1.x);
        float2 b1 = __bfloat1622float2(*(__nv_bfloat162*)&u1.y);
        float2 a2 = __bfloat1622float2(*(__nv_bfloat162*)&u2.x);
        float2 b2 = __bfloat1622float2(*(__nv_bfloat162*)&u2.y);
        float2 a3 = __bfloat1622float2(*(__nv_bfloat162*)&u3.x);
        float2 b3 = __bfloat1622float2(*(__nv_bfloat162*)&u3.y);
        acc.x += a0.x + a1.x + a2.x + a3.x;
        acc.y += a0.y + a1.y + a2.y + a3.y;
        acc.z += b0.x + b1.x + b2.x + b3.x;
        acc.w += b0.y + b1.y + b2.y + b3.y;
    }
    for (; j < end; j++) {
        int s = g_csrc[j];
        uint2 u = *(const uint2*)(hb + (size_t)s * K2 + lane * 4);
        float2 a = __bfloat1622float2(*(__nv_bfloat162*)&u.x);
        float2 b = __bfloat1622float2(*(__nv_bfloat162*)&u.y);
        acc.x += a.x; acc.y += a.y; acc.z += b.x; acc.w += b.y;
    }
    __nv_bfloat162 p0 = __float22bfloat162_rn(make_float2(acc.x, acc.y));
    __nv_bfloat162 p1 = __float22bfloat162_rn(make_float2(acc.z, acc.w));
    uint2 w;
    w.x = *(uint32_t*)&p0;
    w.y = *(uint32_t*)&p1;
    *(uint2*)(hb + (size_t)node * K2 + DIM + lane * 4) = w;
}

// ======================= mma.sync GEMM + fused epilogue =======================
// hout[i][:] = relu( [h|agg][i] @ W2^T + rvec ), colsum accumulated into g_cs[csbuf]
// smem: cs[128] floats @0, A tile @1024 (128 x STRIDE bf16), B tile after.
#define SMEM_CS   0
#define SMEM_A    1024
#define TILE_BYTES (BM * STRIDE * 2)                 // 67584
#define SMEM_B    (SMEM_A + TILE_BYTES)
#define SMEM_TOTAL (SMEM_B + TILE_BYTES)             // ~136 KB

__global__ __launch_bounds__(256) void gemm_mma(const __nv_bfloat16* __restrict__ Ain,
                                                const __nv_bfloat16* __restrict__ W,
                                                __nv_bfloat16* __restrict__ Hout,
                                                int csbuf) {
    extern __shared__ char smem[];
    const uint32_t sb = smem_to_u32(smem);
    const int tid  = threadIdx.x;
    const int wid  = tid >> 5;
    const int lane = tid & 31;
    const int row0 = blockIdx.x * BM;
    const int wm   = wid & 1;    // m block: 64 rows
    const int wn   = wid >> 1;   // n block: 32 cols
    float* css = (float*)(smem + SMEM_CS);

    if (tid < DIM) css[tid] = 0.f;

    // ---- load A tile (node features, zero-padded) and B tile (weights) ----
    #pragma unroll
    for (int it = 0; it < 16; it++) {
        int idx = tid + it * 256;      // 0..4095
        int r = idx >> 5, c8 = idx & 31;
        int node = row0 + r;
        uint4 v = make_uint4(0u, 0u, 0u, 0u);
        if (node < N_NODES) v = *(const uint4*)(Ain + (size_t)node * K2 + c8 * 8);
        *(uint4*)(smem + SMEM_A + (r * STRIDE + c8 * 8) * 2) = v;
    }
    #pragma unroll
    for (int it = 0; it < 16; it++) {
        int idx = tid + it * 256;
        int r = idx >> 5, c8 = idx & 31;
        uint4 v = *(const uint4*)(W + (size_t)r * K2 + c8 * 8);
        *(uint4*)(smem + SMEM_B + (r * STRIDE + c8 * 8) * 2) = v;
    }
    __syncthreads();

    // ---- mma mainloop: warp tile 64(m) x 32(n), K=256 in 16 steps ----
    float acc[4][4][4];
    #pragma unroll
    for (int i = 0; i < 4; i++)
        #pragma unroll
        for (int j = 0; j < 4; j++)
            #pragma unroll
            for (int q = 0; q < 4; q++) acc[i][j][q] = 0.f;

    // ldmatrix lane base addresses (bytes)
    const uint32_t aBase = sb + SMEM_A +
        ((uint32_t)(wm * 64 + (lane & 15)) * STRIDE + ((lane >> 4) * 8)) * 2;
    const uint32_t bBase = sb + SMEM_B +
        ((uint32_t)(wn * 32 + (lane & 7)) * STRIDE + (((lane >> 3) & 1) * 8)) * 2;

    #pragma unroll 4
    for (int kk = 0; kk < 16; kk++) {
        uint32_t af[4][4], bf[4][2];
        #pragma unroll
        for (int i = 0; i < 4; i++)
            ldsm_x4(af[i], aBase + (uint32_t)i * (16 * STRIDE * 2) + kk * 32);
        #pragma unroll
        for (int j = 0; j < 4; j++)
            ldsm_x2(bf[j], bBase + (uint32_t)j * (8 * STRIDE * 2) + kk * 32);
        #pragma unroll
        for (int i = 0; i < 4; i++)
            #pragma unroll
            for (int j = 0; j < 4; j++)
                mma16816(acc[i][j], af[i], bf[j]);
    }

    // ---- epilogue: + rvec, relu, bf16 store, column sums ----
    float rv[4][2];
    #pragma unroll
    for (int j = 0; j < 4; j++) {
        int col = wn * 32 + j * 8 + (lane & 3) * 2;
        rv[j][0] = g_rvec[col];
        rv[j][1] = g_rvec[col + 1];
    }
    float cspart[4][2];
    #pragma unroll
    for (int j = 0; j < 4; j++) { cspart[j][0] = 0.f; cspart[j][1] = 0.f; }

    #pragma unroll
    for (int i = 0; i < 4; i++) {
        int r1 = row0 + wm * 64 + i * 16 + (lane >> 2);
        int r2 = r1 + 8;
        #pragma unroll
        for (int j = 0; j < 4; j++) {
            int col = wn * 32 + j * 8 + (lane & 3) * 2;
            float o0 = fmaxf(acc[i][j][0] + rv[j][0], 0.f);
            float o1 = fmaxf(acc[i][j][1] + rv[j][1], 0.f);
            float o2 = fmaxf(acc[i][j][2] + rv[j][0], 0.f);
            float o3 = fmaxf(acc[i][j][3] + rv[j][1], 0.f);
            if (r1 < N_NODES) {
                __nv_bfloat162 p = __float22bfloat162_rn(make_float2(o0, o1));
                *(uint32_t*)(Hout + (size_t)r1 * K2 + col) = *(uint32_t*)&p;
                cspart[j][0] += o0; cspart[j][1] += o1;
            }
            if (r2 < N_NODES) {
                __nv_bfloat162 p = __float22bfloat162_rn(make_float2(o2, o3));
                *(uint32_t*)(Hout + (size_t)r2 * K2 + col) = *(uint32_t*)&p;
                cspart[j][0] += o2; cspart[j][1] += o3;
            }
        }
    }
    #pragma unroll
    for (int j = 0; j < 4; j++) {
        int col = wn * 32 + j * 8 + (lane & 3) * 2;
        atomicAdd(&css[col], cspart[j][0]);
        atomicAdd(&css[col + 1], cspart[j][1]);
    }
    __syncthreads();
    if (tid < DIM) atomicAdd(&g_cs[csbuf][tid], css[tid]);
}

// ======================= output head =======================
__global__ void out_kernel(const __nv_bfloat16* __restrict__ hb,
                           const float* __restrict__ ow,
                           const float* __restrict__ ob,
                           float* __restrict__ out) {
    int gtid = blockIdx.x * blockDim.x + threadIdx.x;
    int node = gtid >> 5;
    int lane = threadIdx.x & 31;
    if (node >= N_NODES) return;
    uint2 u = *(const uint2*)(hb + (size_t)node * K2 + lane * 4);
    float2 a = __bfloat1622float2(*(__nv_bfloat162*)&u.x);
    float2 b = __bfloat1622float2(*(__nv_bfloat162*)&u.y);
    float4 w0 = *(const float4*)(ow + lane * 4);
    float4 w1 = *(const float4*)(ow + DIM + lane * 4);
    float s0 = a.x * w0.x + a.y * w0.y + b.x * w0.z + b.y * w0.w;
    float s1 = a.x * w1.x + a.y * w1.y + b.x * w1.z + b.y * w1.w;
    #pragma unroll
    for (int off = 16; off > 0; off >>= 1) {
        s0 += __shfl_down_sync(0xffffffffu, s0, off);
        s1 += __shfl_down_sync(0xffffffffu, s1, off);
    }
    if (lane == 0) {
        out[(size_t)node * 2 + 0] = 1.f / (1.f + expf(-(s0 + ob[0])));
        out[(size_t)node * 2 + 1] = 1.f / (1.f + expf(-(s1 + ob[1])));
    }
}

// ======================= launch =======================
extern "C" void kernel_launch(void* const* d_in, const int* in_sizes, int n_in,
                              void* d_out, int out_size) {
    const float* x   = (const float*)d_in[0];
    const int*   src = (const int*)  d_in[1];
    const int*   dst = (const int*)  d_in[2];
    const float* Vw  = (const float*)d_in[3];
    const float* Vb  = (const float*)d_in[4];
    const float* Aw  = (const float*)d_in[5];
    const float* Ab  = (const float*)d_in[6];
    const float* Rw  = (const float*)d_in[7];
    const float* Rb  = (const float*)d_in[8];
    const float* ow  = (const float*)d_in[9];
    const float* ob  = (const float*)d_in[10];
    float* out = (float*)d_out;

    __nv_bfloat16* hbbuf = nullptr;
    cudaGetSymbolAddress((void**)&hbbuf, g_hb);
    __nv_bfloat16* hb0 = hbbuf;
    __nv_bfloat16* hb1 = hbbuf + (size_t)N_NODES * K2;
    __nv_bfloat16* w2buf = nullptr;
    cudaGetSymbolAddress((void**)&w2buf, g_w2);

    cudaFuncSetAttribute(gemm_mma, cudaFuncAttributeMaxDynamicSharedMemorySize, SMEM_TOTAL);

    const int gemm_blocks = (N_NODES + BM - 1) / BM;      // 391
    const int edge_blocks = (N_EDGES + 255) / 256;        // 3125
    const int warp_blocks = (N_NODES * 32 + 255) / 256;   // 6250

    init_kernel<<<64, 256>>>();
    deg_hist_kernel<<<edge_blocks, 256>>>(dst);
    scan_kernel<<<1, 1024>>>();
    fill_kernel<<<edge_blocks, 256>>>(src, dst);
    xconv_kernel<<<512, 128>>>(x);
    w2prep_kernel<<<(3 * DIM * K2 + 255) / 256, 256>>>(Vw, Aw);

    __nv_bfloat16* bufs[2] = {hb0, hb1};
    for (int l = 0; l < 3; l++) {
        int buf = l & 1;
        __nv_bfloat16* hin  = bufs[buf];
        __nv_bfloat16* hout = bufs[buf ^ 1];
        rvec_kernel<<<16, 256>>>(Vb, Ab, Rb, Rw, l, buf);
        gather_kernel<<<warp_blocks, 256>>>(hin);
        gemm_mma<<<gemm_blocks, 256, SMEM_TOTAL>>>(hin, w2buf + (size_t)l * DIM * K2,
                                                   hout, buf ^ 1);
    }
    out_kernel<<<warp_blocks, 256>>>(bufs[1], ow, ob, out);
}